// round 1
// baseline (speedup 1.0000x reference)
#include <cuda_runtime.h>

#define SEQ   256
#define BATCH 8192
#define HID   32

typedef unsigned long long u64;

__device__ __forceinline__ u64 pk(float lo, float hi) {
    u64 r; asm("mov.b64 %0,{%1,%2};" : "=l"(r) : "f"(lo), "f"(hi)); return r;
}
__device__ __forceinline__ void upk(u64 v, float &a, float &b) {
    asm("mov.b64 {%0,%1},%2;" : "=f"(a), "=f"(b) : "l"(v));
}
// Blackwell packed dual-FMA: 2 fp32 FMAs per instruction (only reachable via PTX)
__device__ __forceinline__ void fma2(u64 &acc, u64 a, u64 b) {
    asm("fma.rn.f32x2 %0,%1,%2,%0;" : "+l"(acc) : "l"(a), "l"(b));
}

__device__ __forceinline__ float sigf(float x) {
    return __fdividef(1.0f, 1.0f + __expf(-x));
}
__device__ __forceinline__ float tanh_fast(float x) {
    // tanh(x) = 1 - 2/(e^{2x}+1); exact limits at +-inf, ~1e-6 rel err
    return 1.0f - __fdividef(2.0f, __expf(2.0f * x) + 1.0f);
}

// Block: 128 threads = 4 warps. Each warp handles 4 batch elements.
// Lane layout: t = lane>>2 (0..7) owns hidden units j = 4t..4t+3; g = lane&3 selects element.
__global__ void __launch_bounds__(128) gru2_kernel(
    const float* __restrict__ x,     // (S, B, 1)
    const float* __restrict__ h_in,  // (2, B, 32)
    const float* __restrict__ Wih0,  // (96, 1)
    const float* __restrict__ Whh0,  // (96, 32)
    const float* __restrict__ bih0,  // (96)
    const float* __restrict__ bhh0,  // (96)
    const float* __restrict__ Wih1,  // (96, 32)
    const float* __restrict__ Whh1,  // (96, 32)
    const float* __restrict__ bih1,  // (96)
    const float* __restrict__ bhh1,  // (96)
    const float* __restrict__ Wout,  // (1, 32)
    const float* __restrict__ bout,  // (1)
    float* __restrict__ out)         // y (S*B) then h_state (2*B*32)
{
    // Weight tables, reformatted: float4 chunk index = ((s*4+u)*8+kc)*8 + t
    // so the 8 t-lanes read 8 contiguous 16B chunks (128B, conflict-free),
    // and the 4 g-groups broadcast the same addresses.
    __shared__ __align__(16) float ws0[3072];   // W_hh0
    __shared__ __align__(16) float wsi[3072];   // W_ih1
    __shared__ __align__(16) float wsh[3072];   // W_hh1
    __shared__ __align__(16) float cu[385];     // per-unit constants
    __shared__ __align__(16) float hx[16 * 36]; // h exchange, padded rows (36 floats)

    const int tid = threadIdx.x;

    for (int i = tid; i < 3072; i += 128) {
        int e  = i & 3;
        int tt = (i >> 2) & 7;
        int kc = (i >> 5) & 7;
        int u  = (i >> 8) & 3;
        int s  = i >> 10;
        int row = s * 32 + tt * 4 + u;
        int col = kc * 4 + e;
        ws0[i] = Whh0[row * 32 + col];
        wsi[i] = Wih1[row * 32 + col];
        wsh[i] = Whh1[row * 32 + col];
    }
    if (tid < 32) {
        int j = tid;
        cu[      j] = Wih0[j];
        cu[ 32 + j] = Wih0[32 + j];
        cu[ 64 + j] = Wih0[64 + j];
        cu[ 96 + j] = bih0[j]      + bhh0[j];
        cu[128 + j] = bih0[32 + j] + bhh0[32 + j];
        cu[160 + j] = bih0[64 + j];
        cu[192 + j] = bhh0[64 + j];
        cu[224 + j] = bih1[j]      + bhh1[j];
        cu[256 + j] = bih1[32 + j] + bhh1[32 + j];
        cu[288 + j] = bih1[64 + j];
        cu[320 + j] = bhh1[64 + j];
        cu[352 + j] = Wout[j];
    }
    if (tid == 0) cu[384] = bout[0];
    __syncthreads();

    const int warp = tid >> 5;
    const int lane = tid & 31;
    const int t = lane >> 2;        // 0..7 : hidden-unit group
    const int g = lane & 3;         // 0..3 : batch element within warp
    const int eb = warp * 4 + g;    // element index within block (0..15)
    const int b = blockIdx.x * 16 + eb;

    // per-lane loop-invariant constants (registers)
    float aR[4], aZ[4], aN[4], cR0[4], cZ0[4], cN0[4], cH0[4];
    float cR1[4], cZ1[4], cN1[4], cH1[4], wo[4];
#pragma unroll
    for (int u = 0; u < 4; u++) {
        int j = t * 4 + u;
        aR[u]  = cu[j];        aZ[u]  = cu[32 + j];  aN[u]  = cu[64 + j];
        cR0[u] = cu[96 + j];   cZ0[u] = cu[128 + j];
        cN0[u] = cu[160 + j];  cH0[u] = cu[192 + j];
        cR1[u] = cu[224 + j];  cZ1[u] = cu[256 + j];
        cN1[u] = cu[288 + j];  cH1[u] = cu[320 + j];
        wo[u]  = cu[352 + j];
    }
    const float bo = cu[384];

    // replicated hidden states as f32x2 pairs
    u64 h0p[16], h1p[16];
    {
        const float2* hp = (const float2*)h_in + (size_t)b * 16;
#pragma unroll
        for (int p = 0; p < 16; p++) {
            float2 v0 = hp[p];
            float2 v1 = hp[p + BATCH * 16];
            h0p[p] = pk(v0.x, v0.y);
            h1p[p] = pk(v1.x, v1.y);
        }
    }

    const ulonglong2* w0v = (const ulonglong2*)ws0;
    const ulonglong2* wiv = (const ulonglong2*)wsi;
    const ulonglong2* whv = (const ulonglong2*)wsh;
    float* hxrow = hx + eb * 36;
    const u64* hxr = (const u64*)hxrow;

    float xv = __ldg(x + b);

    for (int st = 0; st < SEQ; st++) {
        float xn = __ldg(x + (size_t)min(st + 1, SEQ - 1) * BATCH + b);

        // ================= layer 0 =================
        float hn0[4];
#pragma unroll
        for (int u = 0; u < 4; u++) {
            u64 ar = 0, az = 0, an = 0;
#pragma unroll
            for (int kc = 0; kc < 8; kc++) {
                ulonglong2 wr = w0v[(((0 * 4 + u) * 8 + kc) << 3) + t];
                ulonglong2 wz = w0v[(((1 * 4 + u) * 8 + kc) << 3) + t];
                ulonglong2 wn = w0v[(((2 * 4 + u) * 8 + kc) << 3) + t];
                u64 ha = h0p[2 * kc], hb = h0p[2 * kc + 1];
                fma2(ar, ha, wr.x); fma2(ar, hb, wr.y);
                fma2(az, ha, wz.x); fma2(az, hb, wz.y);
                fma2(an, ha, wn.x); fma2(an, hb, wn.y);
            }
            float p0, p1;
            upk(ar, p0, p1); float dr = p0 + p1;
            upk(az, p0, p1); float dz = p0 + p1;
            upk(an, p0, p1); float dn = p0 + p1;
            float hlo, hhi; upk(h0p[2 * t + (u >> 1)], hlo, hhi);
            float hold = (u & 1) ? hhi : hlo;
            float r = sigf(fmaf(xv, aR[u], dr + cR0[u]));
            float z = sigf(fmaf(xv, aZ[u], dz + cZ0[u]));
            float n = tanh_fast(fmaf(xv, aN[u], cN0[u]) + r * (dn + cH0[u]));
            hn0[u] = n + z * (hold - n);
        }
        // exchange h0 through padded smem (warp-private region)
        ((float4*)hxrow)[t] = make_float4(hn0[0], hn0[1], hn0[2], hn0[3]);
        __syncwarp();
#pragma unroll
        for (int p = 0; p < 16; p++) h0p[p] = hxr[p];
        __syncwarp();

        // ================= layer 1 =================
        float hn1[4];
#pragma unroll
        for (int u = 0; u < 4; u++) {
            u64 air = 0, aiz = 0, ain = 0, ahr = 0, ahz = 0, ahn = 0;
#pragma unroll
            for (int kc = 0; kc < 8; kc++) {
                ulonglong2 wir = wiv[(((0 * 4 + u) * 8 + kc) << 3) + t];
                ulonglong2 wiz = wiv[(((1 * 4 + u) * 8 + kc) << 3) + t];
                ulonglong2 win = wiv[(((2 * 4 + u) * 8 + kc) << 3) + t];
                ulonglong2 whr = whv[(((0 * 4 + u) * 8 + kc) << 3) + t];
                ulonglong2 whz = whv[(((1 * 4 + u) * 8 + kc) << 3) + t];
                ulonglong2 whn = whv[(((2 * 4 + u) * 8 + kc) << 3) + t];
                u64 ia = h0p[2 * kc], ib = h0p[2 * kc + 1];
                u64 ha = h1p[2 * kc], hb = h1p[2 * kc + 1];
                fma2(air, ia, wir.x); fma2(air, ib, wir.y);
                fma2(aiz, ia, wiz.x); fma2(aiz, ib, wiz.y);
                fma2(ain, ia, win.x); fma2(ain, ib, win.y);
                fma2(ahr, ha, whr.x); fma2(ahr, hb, whr.y);
                fma2(ahz, ha, whz.x); fma2(ahz, hb, whz.y);
                fma2(ahn, ha, whn.x); fma2(ahn, hb, whn.y);
            }
            float p0, p1;
            upk(air, p0, p1); float dir = p0 + p1;
            upk(aiz, p0, p1); float diz = p0 + p1;
            upk(ain, p0, p1); float din = p0 + p1;
            upk(ahr, p0, p1); float dhr = p0 + p1;
            upk(ahz, p0, p1); float dhz = p0 + p1;
            upk(ahn, p0, p1); float dhn = p0 + p1;
            float hlo, hhi; upk(h1p[2 * t + (u >> 1)], hlo, hhi);
            float hold = (u & 1) ? hhi : hlo;
            float r = sigf(dir + dhr + cR1[u]);
            float z = sigf(diz + dhz + cZ1[u]);
            float n = tanh_fast(din + cN1[u] + r * (dhn + cH1[u]));
            hn1[u] = n + z * (hold - n);
        }

        // y = dot(h1_new, Wout) + bout : partial over own units, butterfly over t
        float p = hn1[0] * wo[0] + hn1[1] * wo[1] + hn1[2] * wo[2] + hn1[3] * wo[3];
        p += __shfl_xor_sync(0xffffffffu, p, 4);
        p += __shfl_xor_sync(0xffffffffu, p, 8);
        p += __shfl_xor_sync(0xffffffffu, p, 16);

        // exchange h1
        ((float4*)hxrow)[t] = make_float4(hn1[0], hn1[1], hn1[2], hn1[3]);
        __syncwarp();
#pragma unroll
        for (int p2 = 0; p2 < 16; p2++) h1p[p2] = hxr[p2];
        __syncwarp();

        if (t == 0) out[(size_t)st * BATCH + b] = p + bo;
        xv = xn;
    }

    // final h_state: (2, B, 32) after the y block
    float* hout = out + (size_t)SEQ * BATCH;
    float a0, a1, a2, a3;
    upk(h0p[2 * t], a0, a1); upk(h0p[2 * t + 1], a2, a3);
    ((float4*)(hout + (size_t)b * 32))[t] = make_float4(a0, a1, a2, a3);
    upk(h1p[2 * t], a0, a1); upk(h1p[2 * t + 1], a2, a3);
    ((float4*)(hout + (size_t)BATCH * 32 + (size_t)b * 32))[t] = make_float4(a0, a1, a2, a3);
}

extern "C" void kernel_launch(void* const* d_in, const int* in_sizes, int n_in,
                              void* d_out, int out_size) {
    (void)in_sizes; (void)n_in; (void)out_size;
    const float* x    = (const float*)d_in[0];
    const float* h    = (const float*)d_in[1];
    const float* Wih0 = (const float*)d_in[2];
    const float* Whh0 = (const float*)d_in[3];
    const float* bih0 = (const float*)d_in[4];
    const float* bhh0 = (const float*)d_in[5];
    const float* Wih1 = (const float*)d_in[6];
    const float* Whh1 = (const float*)d_in[7];
    const float* bih1 = (const float*)d_in[8];
    const float* bhh1 = (const float*)d_in[9];
    const float* Wout = (const float*)d_in[10];
    const float* bout = (const float*)d_in[11];

    // 512 blocks x 128 threads: 4 warps/block, 4 batch elems/warp -> 8192 elems
    gru2_kernel<<<512, 128>>>(x, h, Wih0, Whh0, bih0, bhh0,
                              Wih1, Whh1, bih1, bhh1, Wout, bout,
                              (float*)d_out);
}

// round 2
// speedup vs baseline: 1.1747x; 1.1747x over previous
#include <cuda_runtime.h>

#define SEQ   256
#define BATCH 8192

typedef unsigned long long u64;

__device__ __forceinline__ u64 pk(float lo, float hi) {
    u64 r; asm("mov.b64 %0,{%1,%2};" : "=l"(r) : "f"(lo), "f"(hi)); return r;
}
__device__ __forceinline__ void upk(u64 v, float &a, float &b) {
    asm("mov.b64 {%0,%1},%2;" : "=f"(a), "=f"(b) : "l"(v));
}
// Blackwell packed dual-FMA (PTX-only path)
__device__ __forceinline__ void fma2(u64 &acc, u64 a, u64 b) {
    asm("fma.rn.f32x2 %0,%1,%2,%0;" : "+l"(acc) : "l"(a), "l"(b));
}

__device__ __forceinline__ float sigf(float x) {
    return __fdividef(1.0f, 1.0f + __expf(-x));
}
__device__ __forceinline__ float tanh_fast(float x) {
    return 1.0f - __fdividef(2.0f, __expf(2.0f * x) + 1.0f);
}

// Block: 128 threads = 4 warps. Each warp handles 8 batch elements:
// lane: t = lane>>2 (0..7) owns hidden units 4t..4t+3; g = lane&3;
// each lane processes E=2 elements (g and g+4 within the warp's 8).
__global__ void __launch_bounds__(128) gru2_kernel(
    const float* __restrict__ x,     // (S, B, 1)
    const float* __restrict__ h_in,  // (2, B, 32)
    const float* __restrict__ Wih0,  // (96, 1)
    const float* __restrict__ Whh0,  // (96, 32)
    const float* __restrict__ bih0,
    const float* __restrict__ bhh0,
    const float* __restrict__ Wih1,  // (96, 32)
    const float* __restrict__ Whh1,  // (96, 32)
    const float* __restrict__ bih1,
    const float* __restrict__ bhh1,
    const float* __restrict__ Wout,  // (1, 32)
    const float* __restrict__ bout,
    float* __restrict__ out)         // y (S*B) then h_state (2*B*32)
{
    // Weight tables: float4 chunk index = ((gate*4+u)*8+kc)*8 + t
    __shared__ __align__(16) float ws0[3072];   // W_hh0
    __shared__ __align__(16) float wsi[3072];   // W_ih1
    __shared__ __align__(16) float wsh[3072];   // W_hh1
    __shared__ __align__(16) float4 cA4[32];    // (Wih0_r, Wih0_z, Wih0_n, Wout) per unit
    __shared__ __align__(16) float4 cB04[32];   // layer0: (br, bz, bin, bhn)
    __shared__ __align__(16) float4 cB14[32];   // layer1: (br, bz, bin, bhn)
    __shared__ float boS;
    __shared__ __align__(16) float hx[32 * 36]; // h exchange, padded rows

    const int tid = threadIdx.x;

    for (int i = tid; i < 3072; i += 128) {
        int e  = i & 3;
        int tt = (i >> 2) & 7;
        int kc = (i >> 5) & 7;
        int u  = (i >> 8) & 3;
        int s  = i >> 10;
        int row = s * 32 + tt * 4 + u;
        int col = kc * 4 + e;
        ws0[i] = Whh0[row * 32 + col];
        wsi[i] = Wih1[row * 32 + col];
        wsh[i] = Whh1[row * 32 + col];
    }
    if (tid < 32) {
        int j = tid;
        cA4[j]  = make_float4(Wih0[j], Wih0[32 + j], Wih0[64 + j], Wout[j]);
        cB04[j] = make_float4(bih0[j] + bhh0[j], bih0[32 + j] + bhh0[32 + j],
                              bih0[64 + j], bhh0[64 + j]);
        cB14[j] = make_float4(bih1[j] + bhh1[j], bih1[32 + j] + bhh1[32 + j],
                              bih1[64 + j], bhh1[64 + j]);
    }
    if (tid == 0) boS = bout[0];
    __syncthreads();

    const int warp = tid >> 5;
    const int lane = tid & 31;
    const int t = lane >> 2;
    const int g = lane & 3;
    const int eb0 = warp * 8 + g;      // element rows within block (0..31)
    const int eb1 = eb0 + 4;
    const int b0 = blockIdx.x * 32 + eb0;
    const int b1 = b0 + 4;

    // Wout per owned unit (loop-invariant, 4 regs)
    float wo[4];
#pragma unroll
    for (int u = 0; u < 4; u++) wo[u] = cA4[t * 4 + u].w;
    const float bo = boS;

    // hidden states: [elem][pair]
    u64 h0p[2][16], h1p[2][16];
    {
        const float2* hp0 = (const float2*)h_in + (size_t)b0 * 16;
        const float2* hp1 = (const float2*)h_in + (size_t)b1 * 16;
#pragma unroll
        for (int p = 0; p < 16; p++) {
            float2 v;
            v = hp0[p];               h0p[0][p] = pk(v.x, v.y);
            v = hp0[p + BATCH * 16];  h1p[0][p] = pk(v.x, v.y);
            v = hp1[p];               h0p[1][p] = pk(v.x, v.y);
            v = hp1[p + BATCH * 16];  h1p[1][p] = pk(v.x, v.y);
        }
    }

    const ulonglong2* w0v = (const ulonglong2*)ws0;
    const ulonglong2* wiv = (const ulonglong2*)wsi;
    const ulonglong2* whv = (const ulonglong2*)wsh;

    float* hxr0 = hx + eb0 * 36;
    float* hxr1 = hx + eb1 * 36;
    const u64* hxu0 = (const u64*)hxr0;
    const u64* hxu1 = (const u64*)hxr1;

    float xv0 = __ldg(x + b0);
    float xv1 = __ldg(x + b1);

    for (int st = 0; st < SEQ; st++) {
        const size_t nxt = (size_t)min(st + 1, SEQ - 1) * BATCH;
        float xn0 = __ldg(x + nxt + b0);
        float xn1 = __ldg(x + nxt + b1);

        // ================= layer 0 =================
        float hn0[2][4];
#pragma unroll
        for (int u = 0; u < 4; u++) {
            const int j = t * 4 + u;
            u64 ar[2] = {0, 0}, az[2] = {0, 0}, an[2] = {0, 0};
#pragma unroll
            for (int kc = 0; kc < 8; kc++) {
                ulonglong2 wr = w0v[(((0 * 4 + u) * 8 + kc) << 3) + t];
                ulonglong2 wz = w0v[(((1 * 4 + u) * 8 + kc) << 3) + t];
                ulonglong2 wn = w0v[(((2 * 4 + u) * 8 + kc) << 3) + t];
#pragma unroll
                for (int e = 0; e < 2; e++) {
                    u64 ha = h0p[e][2 * kc], hb = h0p[e][2 * kc + 1];
                    fma2(ar[e], ha, wr.x); fma2(ar[e], hb, wr.y);
                    fma2(az[e], ha, wz.x); fma2(az[e], hb, wz.y);
                    fma2(an[e], ha, wn.x); fma2(an[e], hb, wn.y);
                }
            }
            const float4 A = cA4[j];
            const float4 B = cB04[j];
#pragma unroll
            for (int e = 0; e < 2; e++) {
                float p0, p1;
                upk(ar[e], p0, p1); float dr = p0 + p1;
                upk(az[e], p0, p1); float dz = p0 + p1;
                upk(an[e], p0, p1); float dn = p0 + p1;
                float hlo, hhi; upk(h0p[e][2 * t + (u >> 1)], hlo, hhi);
                float hold = (u & 1) ? hhi : hlo;
                float xv = e ? xv1 : xv0;
                float r = sigf(fmaf(xv, A.x, dr + B.x));
                float z = sigf(fmaf(xv, A.y, dz + B.y));
                float n = tanh_fast(fmaf(xv, A.z, B.z) + r * (dn + B.w));
                hn0[e][u] = n + z * (hold - n);
            }
        }
        // exchange h0 (warp-private rows)
        ((float4*)hxr0)[t] = make_float4(hn0[0][0], hn0[0][1], hn0[0][2], hn0[0][3]);
        ((float4*)hxr1)[t] = make_float4(hn0[1][0], hn0[1][1], hn0[1][2], hn0[1][3]);
        __syncwarp();
#pragma unroll
        for (int p = 0; p < 16; p++) { h0p[0][p] = hxu0[p]; h0p[1][p] = hxu1[p]; }
        __syncwarp();

        // ================= layer 1 (fused r/z over [Wih1|Whh1]) =================
        float hn1[2][4];
#pragma unroll
        for (int u = 0; u < 4; u++) {
            const int j = t * 4 + u;
            u64 ar[2] = {0, 0}, az[2] = {0, 0}, ain[2] = {0, 0}, ahn[2] = {0, 0};
#pragma unroll
            for (int kc = 0; kc < 8; kc++) {
                ulonglong2 wir = wiv[(((0 * 4 + u) * 8 + kc) << 3) + t];
                ulonglong2 wiz = wiv[(((1 * 4 + u) * 8 + kc) << 3) + t];
                ulonglong2 win = wiv[(((2 * 4 + u) * 8 + kc) << 3) + t];
                ulonglong2 whr = whv[(((0 * 4 + u) * 8 + kc) << 3) + t];
                ulonglong2 whz = whv[(((1 * 4 + u) * 8 + kc) << 3) + t];
                ulonglong2 whn = whv[(((2 * 4 + u) * 8 + kc) << 3) + t];
#pragma unroll
                for (int e = 0; e < 2; e++) {
                    u64 ia = h0p[e][2 * kc], ib = h0p[e][2 * kc + 1];
                    u64 ha = h1p[e][2 * kc], hb = h1p[e][2 * kc + 1];
                    fma2(ar[e], ia, wir.x); fma2(ar[e], ib, wir.y);
                    fma2(ar[e], ha, whr.x); fma2(ar[e], hb, whr.y);
                    fma2(az[e], ia, wiz.x); fma2(az[e], ib, wiz.y);
                    fma2(az[e], ha, whz.x); fma2(az[e], hb, whz.y);
                    fma2(ain[e], ia, win.x); fma2(ain[e], ib, win.y);
                    fma2(ahn[e], ha, whn.x); fma2(ahn[e], hb, whn.y);
                }
            }
            const float4 C = cB14[j];
#pragma unroll
            for (int e = 0; e < 2; e++) {
                float p0, p1;
                upk(ar[e],  p0, p1); float dr  = p0 + p1;
                upk(az[e],  p0, p1); float dz  = p0 + p1;
                upk(ain[e], p0, p1); float din = p0 + p1;
                upk(ahn[e], p0, p1); float dhn = p0 + p1;
                float hlo, hhi; upk(h1p[e][2 * t + (u >> 1)], hlo, hhi);
                float hold = (u & 1) ? hhi : hlo;
                float r = sigf(dr + C.x);
                float z = sigf(dz + C.y);
                float n = tanh_fast(din + C.z + r * (dhn + C.w));
                hn1[e][u] = n + z * (hold - n);
            }
        }

        // y = dot(h1_new, Wout) + bout per element
        float p0 = hn1[0][0] * wo[0] + hn1[0][1] * wo[1] + hn1[0][2] * wo[2] + hn1[0][3] * wo[3];
        float p1 = hn1[1][0] * wo[0] + hn1[1][1] * wo[1] + hn1[1][2] * wo[2] + hn1[1][3] * wo[3];
        p0 += __shfl_xor_sync(0xffffffffu, p0, 4);
        p0 += __shfl_xor_sync(0xffffffffu, p0, 8);
        p0 += __shfl_xor_sync(0xffffffffu, p0, 16);
        p1 += __shfl_xor_sync(0xffffffffu, p1, 4);
        p1 += __shfl_xor_sync(0xffffffffu, p1, 8);
        p1 += __shfl_xor_sync(0xffffffffu, p1, 16);

        // exchange h1
        ((float4*)hxr0)[t] = make_float4(hn1[0][0], hn1[0][1], hn1[0][2], hn1[0][3]);
        ((float4*)hxr1)[t] = make_float4(hn1[1][0], hn1[1][1], hn1[1][2], hn1[1][3]);
        __syncwarp();
#pragma unroll
        for (int p = 0; p < 16; p++) { h1p[0][p] = hxu0[p]; h1p[1][p] = hxu1[p]; }
        __syncwarp();

        if (t == 0) {
            out[(size_t)st * BATCH + b0] = p0 + bo;
            out[(size_t)st * BATCH + b1] = p1 + bo;
        }
        xv0 = xn0;
        xv1 = xn1;
    }

    // final h_state: (2, B, 32) after y block
    float* hout = out + (size_t)SEQ * BATCH;
    float a0, a1, a2, a3;
#pragma unroll
    for (int e = 0; e < 2; e++) {
        int b = e ? b1 : b0;
        upk(h0p[e][2 * t], a0, a1); upk(h0p[e][2 * t + 1], a2, a3);
        ((float4*)(hout + (size_t)b * 32))[t] = make_float4(a0, a1, a2, a3);
        upk(h1p[e][2 * t], a0, a1); upk(h1p[e][2 * t + 1], a2, a3);
        ((float4*)(hout + (size_t)BATCH * 32 + (size_t)b * 32))[t] = make_float4(a0, a1, a2, a3);
    }
}

extern "C" void kernel_launch(void* const* d_in, const int* in_sizes, int n_in,
                              void* d_out, int out_size) {
    (void)in_sizes; (void)n_in; (void)out_size;
    const float* x    = (const float*)d_in[0];
    const float* h    = (const float*)d_in[1];
    const float* Wih0 = (const float*)d_in[2];
    const float* Whh0 = (const float*)d_in[3];
    const float* bih0 = (const float*)d_in[4];
    const float* bhh0 = (const float*)d_in[5];
    const float* Wih1 = (const float*)d_in[6];
    const float* Whh1 = (const float*)d_in[7];
    const float* bih1 = (const float*)d_in[8];
    const float* bhh1 = (const float*)d_in[9];
    const float* Wout = (const float*)d_in[10];
    const float* bout = (const float*)d_in[11];

    // 256 blocks x 128 threads: 4 warps/block, 8 elems/warp -> 8192 elems
    gru2_kernel<<<256, 128>>>(x, h, Wih0, Whh0, bih0, bhh0,
                              Wih1, Whh1, bih1, bhh1, Wout, bout,
                              (float*)d_out);
}

// round 3
// speedup vs baseline: 1.3838x; 1.1779x over previous
#include <cuda_runtime.h>

#define SEQ   256
#define BATCH 8192

typedef unsigned long long u64;

__device__ __forceinline__ u64 pk(float lo, float hi) {
    u64 r; asm("mov.b64 %0,{%1,%2};" : "=l"(r) : "f"(lo), "f"(hi)); return r;
}
__device__ __forceinline__ void upk(u64 v, float &a, float &b) {
    asm("mov.b64 {%0,%1},%2;" : "=f"(a), "=f"(b) : "l"(v));
}
// Blackwell packed dual-FMA (PTX-only path)
__device__ __forceinline__ void fma2(u64 &acc, u64 a, u64 b) {
    asm("fma.rn.f32x2 %0,%1,%2,%0;" : "+l"(acc) : "l"(a), "l"(b));
}

__device__ __forceinline__ float sigf(float x) {
    return __fdividef(1.0f, 1.0f + __expf(-x));
}
__device__ __forceinline__ float tanh_fast(float x) {
    return 1.0f - __fdividef(2.0f, __expf(2.0f * x) + 1.0f);
}

// Grid: 148 blocks x 224 threads (7 warps) -> exactly 1 block per SM.
// Work unit = 1 warp handling 8 batch elements (E=2 per lane).
// Warp-unit id W = wid*148 + blockIdx.x, active iff W < 1024.
// Lane: t = lane>>2 (0..7) owns hidden units 4t..4t+3; g = lane&3;
// lane processes elements W*8+g and W*8+g+4.
__global__ void __launch_bounds__(224, 1) gru2_kernel(
    const float* __restrict__ x,     // (S, B, 1)
    const float* __restrict__ h_in,  // (2, B, 32)
    const float* __restrict__ Wih0,  // (96, 1)
    const float* __restrict__ Whh0,  // (96, 32)
    const float* __restrict__ bih0,
    const float* __restrict__ bhh0,
    const float* __restrict__ Wih1,  // (96, 32)
    const float* __restrict__ Whh1,  // (96, 32)
    const float* __restrict__ bih1,
    const float* __restrict__ bhh1,
    const float* __restrict__ Wout,  // (1, 32)
    const float* __restrict__ bout,
    float* __restrict__ out)         // y (S*B) then h_state (2*B*32)
{
    // Weight tables: float4 chunk index = ((gate*4+u)*8+kc)*8 + t
    __shared__ __align__(16) float ws0[3072];   // W_hh0
    __shared__ __align__(16) float wsi[3072];   // W_ih1
    __shared__ __align__(16) float wsh[3072];   // W_hh1
    __shared__ __align__(16) float4 cA4[32];    // (Wih0_r, Wih0_z, Wih0_n, Wout)
    __shared__ __align__(16) float4 cB04[32];   // layer0: (br, bz, bin, bhn)
    __shared__ __align__(16) float4 cB14[32];   // layer1: (br, bz, bin, bhn)
    __shared__ float boS;
    __shared__ __align__(16) float hx[56 * 36]; // h exchange rows (7 warps x 8)

    const int tid = threadIdx.x;

    for (int i = tid; i < 3072; i += 224) {
        int e  = i & 3;
        int tt = (i >> 2) & 7;
        int kc = (i >> 5) & 7;
        int u  = (i >> 8) & 3;
        int s  = i >> 10;
        int row = s * 32 + tt * 4 + u;
        int col = kc * 4 + e;
        ws0[i] = Whh0[row * 32 + col];
        wsi[i] = Wih1[row * 32 + col];
        wsh[i] = Whh1[row * 32 + col];
    }
    if (tid < 32) {
        int j = tid;
        cA4[j]  = make_float4(Wih0[j], Wih0[32 + j], Wih0[64 + j], Wout[j]);
        cB04[j] = make_float4(bih0[j] + bhh0[j], bih0[32 + j] + bhh0[32 + j],
                              bih0[64 + j], bhh0[64 + j]);
        cB14[j] = make_float4(bih1[j] + bhh1[j], bih1[32 + j] + bhh1[32 + j],
                              bih1[64 + j], bhh1[64 + j]);
    }
    if (tid == 0) boS = bout[0];
    __syncthreads();

    const int wid  = tid >> 5;
    const int lane = tid & 31;
    const int W = wid * 148 + blockIdx.x;   // warp-unit id
    if (W >= 1024) return;                  // 12 idle warps (after syncthreads)

    const int t = lane >> 2;
    const int g = lane & 3;
    const int b0 = W * 8 + g;
    const int b1 = b0 + 4;

    float wo[4];
#pragma unroll
    for (int u = 0; u < 4; u++) wo[u] = cA4[t * 4 + u].w;
    const float bo = boS;

    // hidden states: [elem][pair]
    u64 h0p[2][16], h1p[2][16];
    {
        const float2* hp0 = (const float2*)h_in + (size_t)b0 * 16;
        const float2* hp1 = (const float2*)h_in + (size_t)b1 * 16;
#pragma unroll
        for (int p = 0; p < 16; p++) {
            float2 v;
            v = hp0[p];               h0p[0][p] = pk(v.x, v.y);
            v = hp0[p + BATCH * 16];  h1p[0][p] = pk(v.x, v.y);
            v = hp1[p];               h0p[1][p] = pk(v.x, v.y);
            v = hp1[p + BATCH * 16];  h1p[1][p] = pk(v.x, v.y);
        }
    }

    const ulonglong2* w0v = (const ulonglong2*)ws0;
    const ulonglong2* wiv = (const ulonglong2*)wsi;
    const ulonglong2* whv = (const ulonglong2*)wsh;

    float* hxr0 = hx + (wid * 8 + g) * 36;
    float* hxr1 = hxr0 + 4 * 36;
    const ulonglong2* hxv0 = (const ulonglong2*)hxr0;
    const ulonglong2* hxv1 = (const ulonglong2*)hxr1;

    float xv0 = __ldg(x + b0);
    float xv1 = __ldg(x + b1);

    for (int st = 0; st < SEQ; st++) {
        const size_t nxt = (size_t)min(st + 1, SEQ - 1) * BATCH;
        float xn0 = __ldg(x + nxt + b0);
        float xn1 = __ldg(x + nxt + b1);

        // ================= layer 0 =================
        float hn0[2][4];
#pragma unroll
        for (int u = 0; u < 4; u++) {
            const int j = t * 4 + u;
            u64 ar[2] = {0, 0}, az[2] = {0, 0}, an[2] = {0, 0};
#pragma unroll
            for (int kc = 0; kc < 8; kc++) {
                ulonglong2 wr = w0v[(((0 * 4 + u) * 8 + kc) << 3) + t];
                ulonglong2 wz = w0v[(((1 * 4 + u) * 8 + kc) << 3) + t];
                ulonglong2 wn = w0v[(((2 * 4 + u) * 8 + kc) << 3) + t];
#pragma unroll
                for (int e = 0; e < 2; e++) {
                    u64 ha = h0p[e][2 * kc], hb = h0p[e][2 * kc + 1];
                    fma2(ar[e], ha, wr.x); fma2(ar[e], hb, wr.y);
                    fma2(az[e], ha, wz.x); fma2(az[e], hb, wz.y);
                    fma2(an[e], ha, wn.x); fma2(an[e], hb, wn.y);
                }
            }
            const float4 A = cA4[j];
            const float4 B = cB04[j];
#pragma unroll
            for (int e = 0; e < 2; e++) {
                float p0, p1;
                upk(ar[e], p0, p1); float dr = p0 + p1;
                upk(az[e], p0, p1); float dz = p0 + p1;
                upk(an[e], p0, p1); float dn = p0 + p1;
                float hlo, hhi; upk(h0p[e][2 * t + (u >> 1)], hlo, hhi);
                float hold = (u & 1) ? hhi : hlo;
                float xv = e ? xv1 : xv0;
                float r = sigf(fmaf(xv, A.x, dr + B.x));
                float z = sigf(fmaf(xv, A.y, dz + B.y));
                float n = tanh_fast(fmaf(xv, A.z, B.z) + r * (dn + B.w));
                hn0[e][u] = n + z * (hold - n);
            }
        }
        // exchange h0 (warp-private rows); read back as 128-bit
        ((float4*)hxr0)[t] = make_float4(hn0[0][0], hn0[0][1], hn0[0][2], hn0[0][3]);
        ((float4*)hxr1)[t] = make_float4(hn0[1][0], hn0[1][1], hn0[1][2], hn0[1][3]);
        __syncwarp();
#pragma unroll
        for (int q = 0; q < 8; q++) {
            ulonglong2 v0 = hxv0[q], v1 = hxv1[q];
            h0p[0][2 * q] = v0.x; h0p[0][2 * q + 1] = v0.y;
            h0p[1][2 * q] = v1.x; h0p[1][2 * q + 1] = v1.y;
        }
        __syncwarp();

        // ================= layer 1 (fused r/z over [Wih1|Whh1]) =================
        float hn1[2][4];
#pragma unroll
        for (int u = 0; u < 4; u++) {
            const int j = t * 4 + u;
            u64 ar[2] = {0, 0}, az[2] = {0, 0}, ain[2] = {0, 0}, ahn[2] = {0, 0};
#pragma unroll
            for (int kc = 0; kc < 8; kc++) {
                ulonglong2 wir = wiv[(((0 * 4 + u) * 8 + kc) << 3) + t];
                ulonglong2 wiz = wiv[(((1 * 4 + u) * 8 + kc) << 3) + t];
                ulonglong2 win = wiv[(((2 * 4 + u) * 8 + kc) << 3) + t];
                ulonglong2 whr = whv[(((0 * 4 + u) * 8 + kc) << 3) + t];
                ulonglong2 whz = whv[(((1 * 4 + u) * 8 + kc) << 3) + t];
                ulonglong2 whn = whv[(((2 * 4 + u) * 8 + kc) << 3) + t];
#pragma unroll
                for (int e = 0; e < 2; e++) {
                    u64 ia = h0p[e][2 * kc], ib = h0p[e][2 * kc + 1];
                    u64 ha = h1p[e][2 * kc], hb = h1p[e][2 * kc + 1];
                    fma2(ar[e], ia, wir.x); fma2(ar[e], ib, wir.y);
                    fma2(ar[e], ha, whr.x); fma2(ar[e], hb, whr.y);
                    fma2(az[e], ia, wiz.x); fma2(az[e], ib, wiz.y);
                    fma2(az[e], ha, whz.x); fma2(az[e], hb, whz.y);
                    fma2(ain[e], ia, win.x); fma2(ain[e], ib, win.y);
                    fma2(ahn[e], ha, whn.x); fma2(ahn[e], hb, whn.y);
                }
            }
            const float4 C = cB14[j];
#pragma unroll
            for (int e = 0; e < 2; e++) {
                float p0, p1;
                upk(ar[e],  p0, p1); float dr  = p0 + p1;
                upk(az[e],  p0, p1); float dz  = p0 + p1;
                upk(ain[e], p0, p1); float din = p0 + p1;
                upk(ahn[e], p0, p1); float dhn = p0 + p1;
                float hlo, hhi; upk(h1p[e][2 * t + (u >> 1)], hlo, hhi);
                float hold = (u & 1) ? hhi : hlo;
                float r = sigf(dr + C.x);
                float z = sigf(dz + C.y);
                float n = tanh_fast(din + C.z + r * (dhn + C.w));
                hn1[e][u] = n + z * (hold - n);
            }
        }

        // y = dot(h1_new, Wout) + bout
        float p0 = hn1[0][0] * wo[0] + hn1[0][1] * wo[1] + hn1[0][2] * wo[2] + hn1[0][3] * wo[3];
        float p1 = hn1[1][0] * wo[0] + hn1[1][1] * wo[1] + hn1[1][2] * wo[2] + hn1[1][3] * wo[3];
        p0 += __shfl_xor_sync(0xffffffffu, p0, 4);
        p0 += __shfl_xor_sync(0xffffffffu, p0, 8);
        p0 += __shfl_xor_sync(0xffffffffu, p0, 16);
        p1 += __shfl_xor_sync(0xffffffffu, p1, 4);
        p1 += __shfl_xor_sync(0xffffffffu, p1, 8);
        p1 += __shfl_xor_sync(0xffffffffu, p1, 16);

        // exchange h1
        ((float4*)hxr0)[t] = make_float4(hn1[0][0], hn1[0][1], hn1[0][2], hn1[0][3]);
        ((float4*)hxr1)[t] = make_float4(hn1[1][0], hn1[1][1], hn1[1][2], hn1[1][3]);
        __syncwarp();
#pragma unroll
        for (int q = 0; q < 8; q++) {
            ulonglong2 v0 = hxv0[q], v1 = hxv1[q];
            h1p[0][2 * q] = v0.x; h1p[0][2 * q + 1] = v0.y;
            h1p[1][2 * q] = v1.x; h1p[1][2 * q + 1] = v1.y;
        }
        __syncwarp();

        if (t == 0) {
            out[(size_t)st * BATCH + b0] = p0 + bo;
            out[(size_t)st * BATCH + b1] = p1 + bo;
        }
        xv0 = xn0;
        xv1 = xn1;
    }

    // final h_state: (2, B, 32) after y block
    float* hout = out + (size_t)SEQ * BATCH;
    float a0, a1, a2, a3;
#pragma unroll
    for (int e = 0; e < 2; e++) {
        int b = e ? b1 : b0;
        upk(h0p[e][2 * t], a0, a1); upk(h0p[e][2 * t + 1], a2, a3);
        ((float4*)(hout + (size_t)b * 32))[t] = make_float4(a0, a1, a2, a3);
        upk(h1p[e][2 * t], a0, a1); upk(h1p[e][2 * t + 1], a2, a3);
        ((float4*)(hout + (size_t)BATCH * 32 + (size_t)b * 32))[t] = make_float4(a0, a1, a2, a3);
    }
}

extern "C" void kernel_launch(void* const* d_in, const int* in_sizes, int n_in,
                              void* d_out, int out_size) {
    (void)in_sizes; (void)n_in; (void)out_size;
    const float* x    = (const float*)d_in[0];
    const float* h    = (const float*)d_in[1];
    const float* Wih0 = (const float*)d_in[2];
    const float* Whh0 = (const float*)d_in[3];
    const float* bih0 = (const float*)d_in[4];
    const float* bhh0 = (const float*)d_in[5];
    const float* Wih1 = (const float*)d_in[6];
    const float* Whh1 = (const float*)d_in[7];
    const float* bih1 = (const float*)d_in[8];
    const float* bhh1 = (const float*)d_in[9];
    const float* Wout = (const float*)d_in[10];
    const float* bout = (const float*)d_in[11];

    // 148 blocks x 7 warps: one block per SM, uniform warp load
    gru2_kernel<<<148, 224>>>(x, h, Wih0, Whh0, bih0, bhh0,
                              Wih1, Whh1, bih1, bhh1, Wout, bout,
                              (float*)d_out);
}

// round 4
// speedup vs baseline: 3.8176x; 2.7589x over previous
#include <cuda_runtime.h>
#include <cstdint>

#define SEQ   256
#define BATCH 8192

__device__ __forceinline__ uint32_t cvtf32(float f) {
    uint32_t u; asm("cvt.rna.tf32.f32 %0, %1;" : "=r"(u) : "f"(f)); return u;
}
__device__ __forceinline__ void mma8(float d[4], const uint32_t* a, uint32_t b0, uint32_t b1) {
    asm("mma.sync.aligned.m16n8k8.row.col.f32.tf32.tf32.f32 "
        "{%0,%1,%2,%3},{%4,%5,%6,%7},{%8,%9},{%0,%1,%2,%3};"
        : "+f"(d[0]), "+f"(d[1]), "+f"(d[2]), "+f"(d[3])
        : "r"(a[0]), "r"(a[1]), "r"(a[2]), "r"(a[3]), "r"(b0), "r"(b1));
}
__device__ __forceinline__ float sigf(float x) {
    return __fdividef(1.0f, 1.0f + __expf(-x));
}
__device__ __forceinline__ float tanh_fast(float x) {
    return 1.0f - __fdividef(2.0f, __expf(2.0f * x) + 1.0f);
}

// Grid: 148 blocks x 128 threads (4 warps). Warp-unit W = wid*148 + bid,
// active iff W < 512; warp owns 16 batch rows [16W, 16W+16).
// Fragment roles per lane: g = lane>>2 (rows g, g+8), tg = lane&3.
__global__ void __launch_bounds__(128, 1) gru2_mma_kernel(
    const float* __restrict__ x,     // (S, B, 1)
    const float* __restrict__ h_in,  // (2, B, 32)
    const float* __restrict__ Wih0,  // (96, 1)
    const float* __restrict__ Whh0,  // (96, 32)
    const float* __restrict__ bih0,
    const float* __restrict__ bhh0,
    const float* __restrict__ Wih1,  // (96, 32)
    const float* __restrict__ Whh1,  // (96, 32)
    const float* __restrict__ bih1,
    const float* __restrict__ bhh1,
    const float* __restrict__ Wout,  // (1, 32)
    const float* __restrict__ bout,
    float* __restrict__ out)         // y (S*B) then h_state (2*B*32)
{
    // B-fragment tables: 72 blocks of 32 uint4. Entry (blk, lane):
    // {W[r][kb+tg], W[r][kb+tg+4], W[r][kb+8+tg], W[r][kb+8+tg+4]} as tf32.
    // blk 0..23  : Whh0, nt=blk>>1 (rows 8nt..), kb=16*(blk&1)        [layer0]
    // blk 24..55 : fused rz K=64: bb=blk-24, nt=bb>>2, kp=bb&3;
    //              kp<2 -> Wih1 else Whh1, kb=16*(kp&1)                [layer1 r,z]
    // blk 56..63 : Wih1 rows 64.., in-gate                             [layer1 i_n]
    // blk 64..71 : Whh1 rows 64.., hn-gate                             [layer1 h_n]
    __shared__ uint4  BW[72 * 32];          // 36864 B
    __shared__ float4 cA4s[32];             // (WihR, WihZ, WihN, bin0)
    __shared__ float4 cB0s[32];             // (br0c, bz0c, bhn0, Wout)
    __shared__ float4 cB1s[32];             // (br1c, bz1c, bin1, bhn1)
    __shared__ float  hs[4 * 16 * 36];      // per-warp h exchange, stride 36
    __shared__ float  boS;

    const int tid = threadIdx.x;

    for (int i = tid; i < 72 * 32; i += 128) {
        int blk = i >> 5, l = i & 31, gg = l >> 2, tt = l & 3;
        const float* Wsrc; int rowb, kb;
        if (blk < 24)      { Wsrc = Whh0; rowb = (blk >> 1) * 8; kb = (blk & 1) * 16; }
        else if (blk < 56) { int bb = blk - 24; int kp = bb & 3;
                             Wsrc = (kp < 2) ? Wih1 : Whh1;
                             rowb = (bb >> 2) * 8; kb = (kp & 1) * 16; }
        else if (blk < 64) { int bb = blk - 56; Wsrc = Wih1; rowb = 64 + (bb >> 1) * 8; kb = (bb & 1) * 16; }
        else               { int bb = blk - 64; Wsrc = Whh1; rowb = 64 + (bb >> 1) * 8; kb = (bb & 1) * 16; }
        const float* wr = Wsrc + (rowb + gg) * 32 + kb + tt;
        BW[i] = make_uint4(cvtf32(wr[0]), cvtf32(wr[4]), cvtf32(wr[8]), cvtf32(wr[12]));
    }
    if (tid < 32) {
        int j = tid;
        cA4s[j] = make_float4(Wih0[j], Wih0[32 + j], Wih0[64 + j], bih0[64 + j]);
        cB0s[j] = make_float4(bih0[j] + bhh0[j], bih0[32 + j] + bhh0[32 + j],
                              bhh0[64 + j], Wout[j]);
        cB1s[j] = make_float4(bih1[j] + bhh1[j], bih1[32 + j] + bhh1[32 + j],
                              bih1[64 + j], bhh1[64 + j]);
    }
    if (tid == 0) boS = bout[0];
    __syncthreads();

    const int wid  = tid >> 5;
    const int lane = tid & 31;
    const int W = wid * 148 + blockIdx.x;
    if (W >= 512) return;

    const int g  = lane >> 2;
    const int tg = lane & 3;
    const int base = W * 16;
    float* hsx = hs + wid * (16 * 36);
    const float bo = boS;

    // loop-invariant Wout for owned columns
    float wo[8];
#pragma unroll
    for (int ut = 0; ut < 4; ut++)
#pragma unroll
        for (int c = 0; c < 2; c++) wo[ut * 2 + c] = cB0s[8 * ut + 2 * tg + c].w;

    // h in D-fragment layout (fp32), index [ut*4 + rr*2 + c]
    float h0D[16], h1D[16];
#pragma unroll
    for (int ut = 0; ut < 4; ut++)
#pragma unroll
        for (int rr = 0; rr < 2; rr++) {
            float2 v0 = *(const float2*)&h_in[(size_t)(base + g + 8 * rr) * 32 + 8 * ut + 2 * tg];
            float2 v1 = *(const float2*)&h_in[(size_t)(BATCH + base + g + 8 * rr) * 32 + 8 * ut + 2 * tg];
            h0D[ut * 4 + rr * 2]     = v0.x; h0D[ut * 4 + rr * 2 + 1] = v0.y;
            h1D[ut * 4 + rr * 2]     = v1.x; h1D[ut * 4 + rr * 2 + 1] = v1.y;
        }

    // h in A-fragment layout (tf32), index [kt*4 + slot]
    uint32_t h0A[16], h1A[16];

#define EXCHANGE(hD, hA)                                                        \
    do {                                                                        \
        _Pragma("unroll")                                                       \
        for (int ut = 0; ut < 4; ut++)                                          \
            _Pragma("unroll")                                                   \
            for (int rr = 0; rr < 2; rr++) {                                    \
                float2 v = make_float2(hD[ut * 4 + rr * 2], hD[ut * 4 + rr * 2 + 1]); \
                *(float2*)&hsx[(g + 8 * rr) * 36 + 8 * ut + 2 * tg] = v;        \
            }                                                                   \
        __syncwarp();                                                           \
        _Pragma("unroll")                                                       \
        for (int kt = 0; kt < 4; kt++) {                                        \
            hA[kt * 4 + 0] = cvtf32(hsx[g * 36 + 8 * kt + tg]);                 \
            hA[kt * 4 + 1] = cvtf32(hsx[(g + 8) * 36 + 8 * kt + tg]);           \
            hA[kt * 4 + 2] = cvtf32(hsx[g * 36 + 8 * kt + tg + 4]);             \
            hA[kt * 4 + 3] = cvtf32(hsx[(g + 8) * 36 + 8 * kt + tg + 4]);       \
        }                                                                       \
        __syncwarp();                                                           \
    } while (0)

    EXCHANGE(h0D, h0A);
    EXCHANGE(h1D, h1A);

    float xc0 = __ldg(x + base + g);
    float xc8 = __ldg(x + base + g + 8);

    for (int st = 0; st < SEQ; st++) {
        const size_t nxt = (size_t)min(st + 1, SEQ - 1) * BATCH;
        float xn0 = __ldg(x + nxt + base + g);
        float xn8 = __ldg(x + nxt + base + g + 8);

        // ============ layer 0: gh = h0 @ Whh0^T  (N=96, K=32) ============
        float D0[12][4];
#pragma unroll
        for (int nt = 0; nt < 12; nt++)
#pragma unroll
            for (int s = 0; s < 4; s++) D0[nt][s] = 0.0f;
#pragma unroll
        for (int nt = 0; nt < 12; nt++)
#pragma unroll
            for (int kp = 0; kp < 2; kp++) {
                uint4 B = BW[(nt * 2 + kp) * 32 + lane];
                mma8(D0[nt], &h0A[(2 * kp) * 4],     B.x, B.y);
                mma8(D0[nt], &h0A[(2 * kp + 1) * 4], B.z, B.w);
            }
        // epilogue L0 (fp32)
#pragma unroll
        for (int ut = 0; ut < 4; ut++)
#pragma unroll
            for (int c = 0; c < 2; c++) {
                const int j = 8 * ut + 2 * tg + c;
                const float4 A  = cA4s[j];
                const float4 Bc = cB0s[j];
#pragma unroll
                for (int rr = 0; rr < 2; rr++) {
                    const float xv = rr ? xc8 : xc0;
                    const int di = rr * 2 + c, hi = ut * 4 + rr * 2 + c;
                    float r = sigf(fmaf(xv, A.x, D0[ut][di] + Bc.x));
                    float z = sigf(fmaf(xv, A.y, D0[ut + 4][di] + Bc.y));
                    float n = tanh_fast(fmaf(xv, A.z, A.w) + r * (D0[ut + 8][di] + Bc.z));
                    float hold = h0D[hi];
                    h0D[hi] = n + z * (hold - n);
                }
            }
        EXCHANGE(h0D, h0A);

        // ============ layer 1 ============
        float Drz[8][4], Din[4][4], Dhn[4][4];
#pragma unroll
        for (int nt = 0; nt < 8; nt++)
#pragma unroll
            for (int s = 0; s < 4; s++) Drz[nt][s] = 0.0f;
#pragma unroll
        for (int nt = 0; nt < 4; nt++)
#pragma unroll
            for (int s = 0; s < 4; s++) { Din[nt][s] = 0.0f; Dhn[nt][s] = 0.0f; }

        // fused r,z: A = [h0'|h1], K=64
#pragma unroll
        for (int nt = 0; nt < 8; nt++)
#pragma unroll
            for (int kp = 0; kp < 4; kp++) {
                uint4 B = BW[(24 + nt * 4 + kp) * 32 + lane];
                const uint32_t* A0 = (kp < 2) ? &h0A[(2 * kp) * 4] : &h1A[(2 * kp - 4) * 4];
                mma8(Drz[nt], A0,     B.x, B.y);
                mma8(Drz[nt], A0 + 4, B.z, B.w);
            }
        // i_n = h0' @ Wih1_n^T
#pragma unroll
        for (int nt = 0; nt < 4; nt++)
#pragma unroll
            for (int kp = 0; kp < 2; kp++) {
                uint4 B = BW[(56 + nt * 2 + kp) * 32 + lane];
                mma8(Din[nt], &h0A[(2 * kp) * 4],     B.x, B.y);
                mma8(Din[nt], &h0A[(2 * kp + 1) * 4], B.z, B.w);
            }
        // h_n = h1 @ Whh1_n^T
#pragma unroll
        for (int nt = 0; nt < 4; nt++)
#pragma unroll
            for (int kp = 0; kp < 2; kp++) {
                uint4 B = BW[(64 + nt * 2 + kp) * 32 + lane];
                mma8(Dhn[nt], &h1A[(2 * kp) * 4],     B.x, B.y);
                mma8(Dhn[nt], &h1A[(2 * kp + 1) * 4], B.z, B.w);
            }

        // epilogue L1 + y projection
        float y0 = 0.0f, y1 = 0.0f;
#pragma unroll
        for (int ut = 0; ut < 4; ut++)
#pragma unroll
            for (int c = 0; c < 2; c++) {
                const int j = 8 * ut + 2 * tg + c;
                const float4 C = cB1s[j];
                const float w = wo[ut * 2 + c];
#pragma unroll
                for (int rr = 0; rr < 2; rr++) {
                    const int di = rr * 2 + c, hi = ut * 4 + rr * 2 + c;
                    float r = sigf(Drz[ut][di] + C.x);
                    float z = sigf(Drz[ut + 4][di] + C.y);
                    float n = tanh_fast(Din[ut][di] + C.z + r * (Dhn[ut][di] + C.w));
                    float hold = h1D[hi];
                    float hn = n + z * (hold - n);
                    h1D[hi] = hn;
                    if (rr) y1 = fmaf(hn, w, y1); else y0 = fmaf(hn, w, y0);
                }
            }
        EXCHANGE(h1D, h1A);

        y0 += __shfl_xor_sync(0xffffffffu, y0, 1);
        y0 += __shfl_xor_sync(0xffffffffu, y0, 2);
        y1 += __shfl_xor_sync(0xffffffffu, y1, 1);
        y1 += __shfl_xor_sync(0xffffffffu, y1, 2);
        if (tg == 0) {
            out[(size_t)st * BATCH + base + g]     = y0 + bo;
            out[(size_t)st * BATCH + base + g + 8] = y1 + bo;
        }
        xc0 = xn0;
        xc8 = xn8;
    }

    // final h_state: (2, B, 32)
    float* hout = out + (size_t)SEQ * BATCH;
#pragma unroll
    for (int ut = 0; ut < 4; ut++)
#pragma unroll
        for (int rr = 0; rr < 2; rr++) {
            size_t r0 = (size_t)(base + g + 8 * rr) * 32 + 8 * ut + 2 * tg;
            *(float2*)&hout[r0] =
                make_float2(h0D[ut * 4 + rr * 2], h0D[ut * 4 + rr * 2 + 1]);
            *(float2*)&hout[(size_t)BATCH * 32 + r0] =
                make_float2(h1D[ut * 4 + rr * 2], h1D[ut * 4 + rr * 2 + 1]);
        }
}

extern "C" void kernel_launch(void* const* d_in, const int* in_sizes, int n_in,
                              void* d_out, int out_size) {
    (void)in_sizes; (void)n_in; (void)out_size;
    const float* x    = (const float*)d_in[0];
    const float* h    = (const float*)d_in[1];
    const float* Wih0 = (const float*)d_in[2];
    const float* Whh0 = (const float*)d_in[3];
    const float* bih0 = (const float*)d_in[4];
    const float* bhh0 = (const float*)d_in[5];
    const float* Wih1 = (const float*)d_in[6];
    const float* Whh1 = (const float*)d_in[7];
    const float* bih1 = (const float*)d_in[8];
    const float* bhh1 = (const float*)d_in[9];
    const float* Wout = (const float*)d_in[10];
    const float* bout = (const float*)d_in[11];

    // 148 blocks x 4 warps: 512 active warps, each on its own SMSP
    gru2_mma_kernel<<<148, 128>>>(x, h, Wih0, Whh0, bih0, bhh0,
                                  Wih1, Whh1, bih1, bhh1, Wout, bout,
                                  (float*)d_out);
}

// round 5
// speedup vs baseline: 3.9633x; 1.0382x over previous
#include <cuda_runtime.h>
#include <cstdint>

#define SEQ   256
#define BATCH 8192

__device__ __forceinline__ uint32_t cvtf32(float f) {
    uint32_t u; asm("cvt.rna.tf32.f32 %0, %1;" : "=r"(u) : "f"(f)); return u;
}
__device__ __forceinline__ void mma8(float d[4], const uint32_t* a, uint32_t b0, uint32_t b1) {
    asm("mma.sync.aligned.m16n8k8.row.col.f32.tf32.tf32.f32 "
        "{%0,%1,%2,%3},{%4,%5,%6,%7},{%8,%9},{%0,%1,%2,%3};"
        : "+f"(d[0]), "+f"(d[1]), "+f"(d[2]), "+f"(d[3])
        : "r"(a[0]), "r"(a[1]), "r"(a[2]), "r"(a[3]), "r"(b0), "r"(b1));
}
// sigmoid(x) = 0.5*tanh(0.5x)+0.5 : single MUFU (tanh.approx), no rcp chain
__device__ __forceinline__ float sig_t(float x) {
    float t; asm("tanh.approx.f32 %0, %1;" : "=f"(t) : "f"(0.5f * x));
    return fmaf(t, 0.5f, 0.5f);
}
// n-gate tanh kept exp-based for accuracy (~1e-6)
__device__ __forceinline__ float tanh_fast(float x) {
    return 1.0f - __fdividef(2.0f, __expf(2.0f * x) + 1.0f);
}

// Grid: 148 blocks x 256 threads (8 warps = 4 pairs). Pair-unit
// P = (wid>>1)*148 + bid, active iff P < 512; pair owns rows [16P,16P+16).
// Within a pair, warp s = wid&1 owns hidden-unit columns [16s, 16s+16).
// Lane roles: g = lane>>2 (rows g, g+8), tg = lane&3.
__global__ void __launch_bounds__(256, 1) gru2_mma2_kernel(
    const float* __restrict__ x,
    const float* __restrict__ h_in,
    const float* __restrict__ Wih0,
    const float* __restrict__ Whh0,
    const float* __restrict__ bih0,
    const float* __restrict__ bhh0,
    const float* __restrict__ Wih1,
    const float* __restrict__ Whh1,
    const float* __restrict__ bih1,
    const float* __restrict__ bhh1,
    const float* __restrict__ Wout,
    const float* __restrict__ bout,
    float* __restrict__ out)
{
    extern __shared__ __align__(16) char smem[];
    uint4*  BW   = (uint4*)smem;               // 72 blk x 32 lanes x 16B = 36864
    float4* cA4s = (float4*)(smem + 36864);    // (WihR,WihZ,WihN,bin0)   512
    float4* cB0s = (float4*)(smem + 37376);    // (br0c,bz0c,bhn0,Wout)   512
    float4* cB1s = (float4*)(smem + 37888);    // (br1c,bz1c,bin1,bhn1)   512
    float*  hs0  = (float*)(smem + 38400);     // 4 pairs x 16x36         9216
    float*  hs1  = (float*)(smem + 47616);     // 9216
    float*  yS   = (float*)(smem + 56832);     // 4 pairs x 2 x 16        512
    float*  boS  = (float*)(smem + 57344);

    const int tid = threadIdx.x;

    // B-fragment table. Per warp-half sHalf, 36 blocks:
    //  0..11 : L0 Whh0   ((gate*2+i)*2+kp), rows gate*32+16s+8i, kb=16kp
    // 12..27 : L1 fused rz over [Wih1|Whh1] K=64 (nt*4+kp)
    // 28..31 : L1 i_n (Wih1 rows 64+16s+8i)
    // 32..35 : L1 h_n (Whh1 rows 64+16s+8i)
    for (int idx = tid; idx < 72 * 32; idx += 256) {
        int blkid = idx >> 5, l = idx & 31, gg = l >> 2, tt = l & 3;
        int sHalf = blkid >= 36, b = blkid - sHalf * 36;
        const float* src; int row, kb;
        if (b < 12) {
            int gate = b >> 2, i = (b >> 1) & 1, kp = b & 1;
            src = Whh0; row = gate * 32 + sHalf * 16 + i * 8; kb = kp * 16;
        } else if (b < 28) {
            int bb = b - 12, nt = bb >> 2, kp = bb & 3;
            int gate = nt >> 1, i = nt & 1;
            src = (kp < 2) ? Wih1 : Whh1;
            row = gate * 32 + sHalf * 16 + i * 8; kb = (kp & 1) * 16;
        } else if (b < 32) {
            int bb = b - 28, i = bb >> 1, kp = bb & 1;
            src = Wih1; row = 64 + sHalf * 16 + i * 8; kb = kp * 16;
        } else {
            int bb = b - 32, i = bb >> 1, kp = bb & 1;
            src = Whh1; row = 64 + sHalf * 16 + i * 8; kb = kp * 16;
        }
        const float* wr = src + (row + gg) * 32 + kb + tt;
        BW[idx] = make_uint4(cvtf32(wr[0]), cvtf32(wr[4]), cvtf32(wr[8]), cvtf32(wr[12]));
    }
    if (tid < 32) {
        int j = tid;
        cA4s[j] = make_float4(Wih0[j], Wih0[32 + j], Wih0[64 + j], bih0[64 + j]);
        cB0s[j] = make_float4(bih0[j] + bhh0[j], bih0[32 + j] + bhh0[32 + j],
                              bhh0[64 + j], Wout[j]);
        cB1s[j] = make_float4(bih1[j] + bhh1[j], bih1[32 + j] + bhh1[32 + j],
                              bih1[64 + j], bhh1[64 + j]);
    }
    if (tid == 0) boS[0] = bout[0];
    __syncthreads();

    const int wid  = tid >> 5;
    const int lane = tid & 31;
    const int pib  = wid >> 1;        // pair within block (0..3)
    const int s    = wid & 1;         // column-half
    const int P    = pib * 148 + blockIdx.x;
    if (P >= 512) return;

    const int g  = lane >> 2;
    const int tg = lane & 3;
    const int base = P * 16;
    const int barId = 1 + pib;
    const int colb = s * 16;
    float* hx0 = hs0 + pib * 576;
    float* hx1 = hs1 + pib * 576;
    float* yP  = yS  + pib * 32;
    const uint4* BWs = BW + s * 36 * 32;
    const float bo = boS[0];

#define BARP() asm volatile("bar.sync %0, 64;" :: "r"(barId) : "memory")

    // per-lane constants for owned columns (idx = i*2+c, col = colb+8i+2tg+c)
    float4 cAr[4], cB0r[4], cB1r[4];
#pragma unroll
    for (int i = 0; i < 2; i++)
#pragma unroll
        for (int c = 0; c < 2; c++) {
            int j = colb + i * 8 + 2 * tg + c;
            cAr[i * 2 + c]  = cA4s[j];
            cB0r[i * 2 + c] = cB0s[j];
            cB1r[i * 2 + c] = cB1s[j];
        }

    // h in D-layout (own 16 cols): index i*4 + rr*2 + c
    float h0D[8], h1D[8];
#pragma unroll
    for (int i = 0; i < 2; i++)
#pragma unroll
        for (int rr = 0; rr < 2; rr++) {
            size_t r0 = (size_t)(base + g + 8 * rr) * 32 + colb + i * 8 + 2 * tg;
            float2 v0 = *(const float2*)&h_in[r0];
            float2 v1 = *(const float2*)&h_in[(size_t)BATCH * 32 + r0];
            h0D[i * 4 + rr * 2] = v0.x; h0D[i * 4 + rr * 2 + 1] = v0.y;
            h1D[i * 4 + rr * 2] = v1.x; h1D[i * 4 + rr * 2 + 1] = v1.y;
        }

    uint32_t h0A[16], h1A[16];   // full-K A fragments

#define STORE_H(hD, hx)                                                          \
    do {                                                                         \
        _Pragma("unroll")                                                        \
        for (int i = 0; i < 2; i++)                                              \
            _Pragma("unroll")                                                    \
            for (int rr = 0; rr < 2; rr++)                                       \
                *(float2*)&hx[(g + 8 * rr) * 36 + colb + i * 8 + 2 * tg] =       \
                    make_float2(hD[i * 4 + rr * 2], hD[i * 4 + rr * 2 + 1]);     \
    } while (0)

#define LOAD_A(hx, hA)                                                           \
    do {                                                                         \
        _Pragma("unroll")                                                        \
        for (int kt = 0; kt < 4; kt++) {                                         \
            hA[kt * 4 + 0] = cvtf32(hx[g * 36 + 8 * kt + tg]);                   \
            hA[kt * 4 + 1] = cvtf32(hx[(g + 8) * 36 + 8 * kt + tg]);             \
            hA[kt * 4 + 2] = cvtf32(hx[g * 36 + 8 * kt + tg + 4]);               \
            hA[kt * 4 + 3] = cvtf32(hx[(g + 8) * 36 + 8 * kt + tg + 4]);         \
        }                                                                        \
    } while (0)

    STORE_H(h0D, hx0);
    STORE_H(h1D, hx1);
    BARP();
    LOAD_A(hx0, h0A);
    LOAD_A(hx1, h1A);

    float xc0 = __ldg(x + base + g);
    float xc8 = __ldg(x + base + g + 8);

    for (int st = 0; st < SEQ; st++) {
        const size_t nxt = (size_t)min(st + 1, SEQ - 1) * BATCH;
        float xn0 = __ldg(x + nxt + base + g);
        float xn8 = __ldg(x + nxt + base + g + 8);

        // ---------- layer 0: own 48 gate rows, 12 MMAs ----------
        float D0[6][4];
#pragma unroll
        for (int q = 0; q < 6; q++)
#pragma unroll
            for (int v = 0; v < 4; v++) D0[q][v] = 0.0f;
#pragma unroll
        for (int gate = 0; gate < 3; gate++)
#pragma unroll
            for (int i = 0; i < 2; i++)
#pragma unroll
                for (int kp = 0; kp < 2; kp++) {
                    uint4 B = BWs[(gate * 4 + i * 2 + kp) * 32 + lane];
                    mma8(D0[gate * 2 + i], &h0A[(2 * kp) * 4],     B.x, B.y);
                    mma8(D0[gate * 2 + i], &h0A[(2 * kp + 1) * 4], B.z, B.w);
                }
#pragma unroll
        for (int i = 0; i < 2; i++)
#pragma unroll
            for (int c = 0; c < 2; c++) {
                const float4 A  = cAr[i * 2 + c];
                const float4 Bc = cB0r[i * 2 + c];
#pragma unroll
                for (int rr = 0; rr < 2; rr++) {
                    const float xv = rr ? xc8 : xc0;
                    const int di = rr * 2 + c, hi = i * 4 + rr * 2 + c;
                    float r = sig_t(fmaf(xv, A.x, D0[i][di] + Bc.x));
                    float z = sig_t(fmaf(xv, A.y, D0[2 + i][di] + Bc.y));
                    float n = tanh_fast(fmaf(xv, A.z, A.w) + r * (D0[4 + i][di] + Bc.z));
                    float hold = h0D[hi];
                    h0D[hi] = n + z * (hold - n);
                }
            }
        STORE_H(h0D, hx0);
        BARP();
        LOAD_A(hx0, h0A);

        // ---------- layer 1: 24 MMAs ----------
        float Drz[4][4], Din[2][4], Dhn[2][4];
#pragma unroll
        for (int q = 0; q < 4; q++)
#pragma unroll
            for (int v = 0; v < 4; v++) Drz[q][v] = 0.0f;
#pragma unroll
        for (int q = 0; q < 2; q++)
#pragma unroll
            for (int v = 0; v < 4; v++) { Din[q][v] = 0.0f; Dhn[q][v] = 0.0f; }

#pragma unroll
        for (int nt = 0; nt < 4; nt++)
#pragma unroll
            for (int kp = 0; kp < 4; kp++) {
                uint4 B = BWs[(12 + nt * 4 + kp) * 32 + lane];
                const uint32_t* A0 = (kp < 2) ? &h0A[(2 * kp) * 4]
                                              : &h1A[(2 * kp - 4) * 4];
                mma8(Drz[nt], A0,     B.x, B.y);
                mma8(Drz[nt], A0 + 4, B.z, B.w);
            }
#pragma unroll
        for (int nt = 0; nt < 2; nt++)
#pragma unroll
            for (int kp = 0; kp < 2; kp++) {
                uint4 B = BWs[(28 + nt * 2 + kp) * 32 + lane];
                mma8(Din[nt], &h0A[(2 * kp) * 4],     B.x, B.y);
                mma8(Din[nt], &h0A[(2 * kp + 1) * 4], B.z, B.w);
            }
#pragma unroll
        for (int nt = 0; nt < 2; nt++)
#pragma unroll
            for (int kp = 0; kp < 2; kp++) {
                uint4 B = BWs[(32 + nt * 2 + kp) * 32 + lane];
                mma8(Dhn[nt], &h1A[(2 * kp) * 4],     B.x, B.y);
                mma8(Dhn[nt], &h1A[(2 * kp + 1) * 4], B.z, B.w);
            }

        float y0 = 0.0f, y1 = 0.0f;
#pragma unroll
        for (int i = 0; i < 2; i++)
#pragma unroll
            for (int c = 0; c < 2; c++) {
                const float4 C = cB1r[i * 2 + c];
                const float w = cB0r[i * 2 + c].w;
#pragma unroll
                for (int rr = 0; rr < 2; rr++) {
                    const int di = rr * 2 + c, hi = i * 4 + rr * 2 + c;
                    float r = sig_t(Drz[i][di] + C.x);
                    float z = sig_t(Drz[2 + i][di] + C.y);
                    float n = tanh_fast(Din[i][di] + C.z + r * (Dhn[i][di] + C.w));
                    float hold = h1D[hi];
                    float hn = n + z * (hold - n);
                    h1D[hi] = hn;
                    if (rr) y1 = fmaf(hn, w, y1); else y0 = fmaf(hn, w, y0);
                }
            }
        STORE_H(h1D, hx1);
        y0 += __shfl_xor_sync(0xffffffffu, y0, 1);
        y0 += __shfl_xor_sync(0xffffffffu, y0, 2);
        y1 += __shfl_xor_sync(0xffffffffu, y1, 1);
        y1 += __shfl_xor_sync(0xffffffffu, y1, 2);
        if (tg == 0) { yP[s * 16 + g] = y0; yP[s * 16 + g + 8] = y1; }
        BARP();
        LOAD_A(hx1, h1A);
        if (s == 0 && tg == 0) {
            out[(size_t)st * BATCH + base + g]     = yP[g]     + yP[16 + g]     + bo;
            out[(size_t)st * BATCH + base + g + 8] = yP[g + 8] + yP[16 + g + 8] + bo;
        }
        xc0 = xn0;
        xc8 = xn8;
    }

    // final h_state (2, B, 32): each warp writes its own 16 columns
    float* hout = out + (size_t)SEQ * BATCH;
#pragma unroll
    for (int i = 0; i < 2; i++)
#pragma unroll
        for (int rr = 0; rr < 2; rr++) {
            size_t r0 = (size_t)(base + g + 8 * rr) * 32 + colb + i * 8 + 2 * tg;
            *(float2*)&hout[r0] =
                make_float2(h0D[i * 4 + rr * 2], h0D[i * 4 + rr * 2 + 1]);
            *(float2*)&hout[(size_t)BATCH * 32 + r0] =
                make_float2(h1D[i * 4 + rr * 2], h1D[i * 4 + rr * 2 + 1]);
        }
#undef BARP
#undef STORE_H
#undef LOAD_A
}

extern "C" void kernel_launch(void* const* d_in, const int* in_sizes, int n_in,
                              void* d_out, int out_size) {
    (void)in_sizes; (void)n_in; (void)out_size;
    const float* x    = (const float*)d_in[0];
    const float* h    = (const float*)d_in[1];
    const float* Wih0 = (const float*)d_in[2];
    const float* Whh0 = (const float*)d_in[3];
    const float* bih0 = (const float*)d_in[4];
    const float* bhh0 = (const float*)d_in[5];
    const float* Wih1 = (const float*)d_in[6];
    const float* Whh1 = (const float*)d_in[7];
    const float* bih1 = (const float*)d_in[8];
    const float* bhh1 = (const float*)d_in[9];
    const float* Wout = (const float*)d_in[10];
    const float* bout = (const float*)d_in[11];

    const int smemBytes = 57472;
    cudaFuncSetAttribute(gru2_mma2_kernel,
                         cudaFuncAttributeMaxDynamicSharedMemorySize, smemBytes);
    // 148 blocks x 8 warps (4 pairs): 1024 active warps, 2 per SMSP
    gru2_mma2_kernel<<<148, 256, smemBytes>>>(x, h, Wih0, Whh0, bih0, bhh0,
                                              Wih1, Whh1, bih1, bhh1, Wout, bout,
                                              (float*)d_out);
}

// round 6
// speedup vs baseline: 6.3913x; 1.6126x over previous
#include <cuda_runtime.h>
#include <cstdint>

#define SEQ   256
#define BATCH 8192

// pack two f32 -> f16x2 (lo = first arg)
__device__ __forceinline__ uint32_t pkh(float lo, float hi) {
    uint32_t u; asm("cvt.rn.f16x2.f32 %0, %2, %1;" : "=r"(u) : "f"(lo), "f"(hi)); return u;
}
__device__ __forceinline__ void mma16(float d[4], const uint32_t a[4], uint32_t b0, uint32_t b1) {
    asm("mma.sync.aligned.m16n8k16.row.col.f32.f16.f16.f32 "
        "{%0,%1,%2,%3},{%4,%5,%6,%7},{%8,%9},{%0,%1,%2,%3};"
        : "+f"(d[0]), "+f"(d[1]), "+f"(d[2]), "+f"(d[3])
        : "r"(a[0]), "r"(a[1]), "r"(a[2]), "r"(a[3]), "r"(b0), "r"(b1));
}
// sigmoid(x) = 0.5*tanh(0.5x)+0.5 : single MUFU
__device__ __forceinline__ float sig_t(float x) {
    float t; asm("tanh.approx.f32 %0, %1;" : "=f"(t) : "f"(0.5f * x));
    return fmaf(t, 0.5f, 0.5f);
}
__device__ __forceinline__ float tanh_ap(float x) {
    float t; asm("tanh.approx.f32 %0, %1;" : "=f"(t) : "f"(x)); return t;
}

// Grid: 148 blocks x 256 threads (8 warps = 4 pairs). Pair-unit
// P = (wid>>1)*148 + bid, active iff P < 512; pair owns rows [16P,16P+16).
// Warp s = wid&1 owns hidden-unit columns [16s,16s+16).
// Lane: g = lane>>2 (rows g, g+8), tg = lane&3.
__global__ void __launch_bounds__(256, 1) gru2_hmma_kernel(
    const float* __restrict__ x,
    const float* __restrict__ h_in,
    const float* __restrict__ Wih0,
    const float* __restrict__ Whh0,
    const float* __restrict__ bih0,
    const float* __restrict__ bhh0,
    const float* __restrict__ Wih1,
    const float* __restrict__ Whh1,
    const float* __restrict__ bih1,
    const float* __restrict__ bhh1,
    const float* __restrict__ Wout,
    const float* __restrict__ bout,
    float* __restrict__ out)
{
    // fp16 B-fragment table: per half s, 18 uint4-slots x 32 lanes.
    // Each slot = one 8-row n-tile x K=32 (2 k16 chunks): {b0k0,b1k0,b0k1,b1k1}.
    //  slot 0..5  : L0 Whh0, rows (slot>>1)*32 + 16s + (slot&1)*8
    //  slot 6..13 : L1 r/z, q=slot-6, nt=q>>1 (gate=nt>>1,i=nt&1),
    //               q even -> Wih1, odd -> Whh1; rows gate*32+16s+8i
    //  slot 14,15 : L1 i_n, Wih1 rows 64+16s+8i
    //  slot 16,17 : L1 h_n, Whh1 rows 64+16s+8i
    __shared__ __align__(16) uint4  BW[36 * 32];      // 18432 B
    __shared__ float4 cA4s[32];                        // (WihR,WihZ,WihN,bin0)
    __shared__ float4 cB0s[32];                        // (br0c,bz0c,bhn0,Wout)
    __shared__ float4 cB1s[32];                        // (br1c,bz1c,bin1,bhn1)
    __shared__ uint32_t hs0[4 * 16 * 20];              // f16x2 h0, stride 20/row
    __shared__ uint32_t hs1[4 * 16 * 20];              // f16x2 h1
    __shared__ float  yS[4 * 32];
    __shared__ float  boS;

    const int tid = threadIdx.x;

    for (int idx = tid; idx < 36 * 32; idx += 256) {
        int blkid = idx >> 5, l = idx & 31, gg = l >> 2, tt = l & 3;
        int sH = blkid >= 18, slot = blkid - sH * 18;
        const float* src; int rowb;
        if (slot < 6) {
            src = Whh0; rowb = (slot >> 1) * 32 + sH * 16 + (slot & 1) * 8;
        } else if (slot < 14) {
            int q = slot - 6, nt = q >> 1;
            src = (q & 1) ? Whh1 : Wih1;
            rowb = (nt >> 1) * 32 + sH * 16 + (nt & 1) * 8;
        } else if (slot < 16) {
            src = Wih1; rowb = 64 + sH * 16 + (slot - 14) * 8;
        } else {
            src = Whh1; rowb = 64 + sH * 16 + (slot - 16) * 8;
        }
        const float* wr = src + (rowb + gg) * 32 + 2 * tt;
        BW[idx] = make_uint4(pkh(wr[0],  wr[1]),  pkh(wr[8],  wr[9]),
                             pkh(wr[16], wr[17]), pkh(wr[24], wr[25]));
    }
    if (tid < 32) {
        int j = tid;
        cA4s[j] = make_float4(Wih0[j], Wih0[32 + j], Wih0[64 + j], bih0[64 + j]);
        cB0s[j] = make_float4(bih0[j] + bhh0[j], bih0[32 + j] + bhh0[32 + j],
                              bhh0[64 + j], Wout[j]);
        cB1s[j] = make_float4(bih1[j] + bhh1[j], bih1[32 + j] + bhh1[32 + j],
                              bih1[64 + j], bhh1[64 + j]);
    }
    if (tid == 0) boS = bout[0];
    __syncthreads();

    const int wid  = tid >> 5;
    const int lane = tid & 31;
    const int pib  = wid >> 1;
    const int s    = wid & 1;
    const int P    = pib * 148 + blockIdx.x;
    if (P >= 512) return;

    const int g  = lane >> 2;
    const int tg = lane & 3;
    const int base = P * 16;
    const int barId = 1 + pib;
    const int colb = s * 16;
    uint32_t* hx0 = hs0 + pib * 320;
    uint32_t* hx1 = hs1 + pib * 320;
    float* yP = yS + pib * 32;
    const uint4* BWs = BW + s * 18 * 32;
    const float bo = boS;

#define BARP() asm volatile("bar.sync %0, 64;" :: "r"(barId) : "memory")

    // per-lane gate constants for owned columns (idx i*2+c, col = colb+8i+2tg+c)
    float4 cAr[4], cB0r[4], cB1r[4];
#pragma unroll
    for (int i = 0; i < 2; i++)
#pragma unroll
        for (int c = 0; c < 2; c++) {
            int j = colb + i * 8 + 2 * tg + c;
            cAr[i * 2 + c]  = cA4s[j];
            cB0r[i * 2 + c] = cB0s[j];
            cB1r[i * 2 + c] = cB1s[j];
        }

    // h in D-layout (fp32, own 16 cols): index i*4 + rr*2 + c
    float h0D[8], h1D[8];
#pragma unroll
    for (int i = 0; i < 2; i++)
#pragma unroll
        for (int rr = 0; rr < 2; rr++) {
            size_t r0 = (size_t)(base + g + 8 * rr) * 32 + colb + i * 8 + 2 * tg;
            float2 v0 = *(const float2*)&h_in[r0];
            float2 v1 = *(const float2*)&h_in[(size_t)BATCH * 32 + r0];
            h0D[i * 4 + rr * 2] = v0.x; h0D[i * 4 + rr * 2 + 1] = v0.y;
            h1D[i * 4 + rr * 2] = v1.x; h1D[i * 4 + rr * 2 + 1] = v1.y;
        }

    uint32_t h0A[8], h1A[8];   // fp16 A fragments, [kp*4 + slot]

#define STORE_H(hD, hx)                                                          \
    do {                                                                         \
        _Pragma("unroll")                                                        \
        for (int i = 0; i < 2; i++)                                              \
            _Pragma("unroll")                                                    \
            for (int rr = 0; rr < 2; rr++)                                       \
                hx[(g + 8 * rr) * 20 + 8 * s + 4 * i + tg] =                     \
                    pkh(hD[i * 4 + rr * 2], hD[i * 4 + rr * 2 + 1]);             \
    } while (0)

#define LOAD_A(hx, hA)                                                           \
    do {                                                                         \
        _Pragma("unroll")                                                        \
        for (int kp = 0; kp < 2; kp++) {                                         \
            hA[kp * 4 + 0] = hx[g * 20 + tg + 8 * kp];                           \
            hA[kp * 4 + 1] = hx[(g + 8) * 20 + tg + 8 * kp];                     \
            hA[kp * 4 + 2] = hx[g * 20 + tg + 4 + 8 * kp];                       \
            hA[kp * 4 + 3] = hx[(g + 8) * 20 + tg + 4 + 8 * kp];                 \
        }                                                                        \
    } while (0)

    STORE_H(h0D, hx0);
    STORE_H(h1D, hx1);
    BARP();
    LOAD_A(hx0, h0A);
    LOAD_A(hx1, h1A);

    float xc0 = __ldg(x + base + g);
    float xc8 = __ldg(x + base + g + 8);

    for (int st = 0; st < SEQ; st++) {
        const size_t nxt = (size_t)min(st + 1, SEQ - 1) * BATCH;
        float xn0 = __ldg(x + nxt + base + g);
        float xn8 = __ldg(x + nxt + base + g + 8);

        // ---------- layer 0: 6 n-tiles, 12 MMAs ----------
        float D0[6][4];
#pragma unroll
        for (int q = 0; q < 6; q++)
#pragma unroll
            for (int v = 0; v < 4; v++) D0[q][v] = 0.0f;
#pragma unroll
        for (int nt = 0; nt < 6; nt++) {
            uint4 B = BWs[nt * 32 + lane];
            mma16(D0[nt], &h0A[0], B.x, B.y);
            mma16(D0[nt], &h0A[4], B.z, B.w);
        }
#pragma unroll
        for (int i = 0; i < 2; i++)
#pragma unroll
            for (int c = 0; c < 2; c++) {
                const float4 A  = cAr[i * 2 + c];
                const float4 Bc = cB0r[i * 2 + c];
#pragma unroll
                for (int rr = 0; rr < 2; rr++) {
                    const float xv = rr ? xc8 : xc0;
                    const int di = rr * 2 + c, hi = i * 4 + rr * 2 + c;
                    float r = sig_t(fmaf(xv, A.x, D0[i][di] + Bc.x));
                    float z = sig_t(fmaf(xv, A.y, D0[2 + i][di] + Bc.y));
                    float n = tanh_ap(fmaf(xv, A.z, A.w) + r * (D0[4 + i][di] + Bc.z));
                    float hold = h0D[hi];
                    h0D[hi] = n + z * (hold - n);
                }
            }
        STORE_H(h0D, hx0);
        BARP();
        LOAD_A(hx0, h0A);

        // ---------- layer 1: 24 MMAs ----------
        float Drz[4][4], Din[2][4], Dhn[2][4];
#pragma unroll
        for (int q = 0; q < 4; q++)
#pragma unroll
            for (int v = 0; v < 4; v++) Drz[q][v] = 0.0f;
#pragma unroll
        for (int q = 0; q < 2; q++)
#pragma unroll
            for (int v = 0; v < 4; v++) { Din[q][v] = 0.0f; Dhn[q][v] = 0.0f; }

#pragma unroll
        for (int nt = 0; nt < 4; nt++) {
            uint4 Bi = BWs[(6 + nt * 2) * 32 + lane];       // Wih1 chunk, A=h0'
            uint4 Bh = BWs[(6 + nt * 2 + 1) * 32 + lane];   // Whh1 chunk, A=h1
            mma16(Drz[nt], &h0A[0], Bi.x, Bi.y);
            mma16(Drz[nt], &h0A[4], Bi.z, Bi.w);
            mma16(Drz[nt], &h1A[0], Bh.x, Bh.y);
            mma16(Drz[nt], &h1A[4], Bh.z, Bh.w);
        }
#pragma unroll
        for (int i = 0; i < 2; i++) {
            uint4 B = BWs[(14 + i) * 32 + lane];
            mma16(Din[i], &h0A[0], B.x, B.y);
            mma16(Din[i], &h0A[4], B.z, B.w);
        }
#pragma unroll
        for (int i = 0; i < 2; i++) {
            uint4 B = BWs[(16 + i) * 32 + lane];
            mma16(Dhn[i], &h1A[0], B.x, B.y);
            mma16(Dhn[i], &h1A[4], B.z, B.w);
        }

        float y0 = 0.0f, y1 = 0.0f;
#pragma unroll
        for (int i = 0; i < 2; i++)
#pragma unroll
            for (int c = 0; c < 2; c++) {
                const float4 C = cB1r[i * 2 + c];
                const float w = cB0r[i * 2 + c].w;
#pragma unroll
                for (int rr = 0; rr < 2; rr++) {
                    const int di = rr * 2 + c, hi = i * 4 + rr * 2 + c;
                    float r = sig_t(Drz[i][di] + C.x);      // Drz[0..1] = r
                    float z = sig_t(Drz[2 + i][di] + C.y);  // Drz[2..3] = z
                    float n = tanh_ap(Din[i][di] + C.z + r * (Dhn[i][di] + C.w));
                    float hold = h1D[hi];
                    float hn = n + z * (hold - n);
                    h1D[hi] = hn;
                    if (rr) y1 = fmaf(hn, w, y1); else y0 = fmaf(hn, w, y0);
                }
            }
        STORE_H(h1D, hx1);
        y0 += __shfl_xor_sync(0xffffffffu, y0, 1);
        y0 += __shfl_xor_sync(0xffffffffu, y0, 2);
        y1 += __shfl_xor_sync(0xffffffffu, y1, 1);
        y1 += __shfl_xor_sync(0xffffffffu, y1, 2);
        if (tg == 0) { yP[s * 16 + g] = y0; yP[s * 16 + g + 8] = y1; }
        BARP();
        LOAD_A(hx1, h1A);
        if (s == 0 && tg == 0) {
            out[(size_t)st * BATCH + base + g]     = yP[g]     + yP[16 + g]     + bo;
            out[(size_t)st * BATCH + base + g + 8] = yP[g + 8] + yP[16 + g + 8] + bo;
        }
        xc0 = xn0;
        xc8 = xn8;
    }

    // final h_state (2, B, 32)
    float* hout = out + (size_t)SEQ * BATCH;
#pragma unroll
    for (int i = 0; i < 2; i++)
#pragma unroll
        for (int rr = 0; rr < 2; rr++) {
            size_t r0 = (size_t)(base + g + 8 * rr) * 32 + colb + i * 8 + 2 * tg;
            *(float2*)&hout[r0] =
                make_float2(h0D[i * 4 + rr * 2], h0D[i * 4 + rr * 2 + 1]);
            *(float2*)&hout[(size_t)BATCH * 32 + r0] =
                make_float2(h1D[i * 4 + rr * 2], h1D[i * 4 + rr * 2 + 1]);
        }
#undef BARP
#undef STORE_H
#undef LOAD_A
}

extern "C" void kernel_launch(void* const* d_in, const int* in_sizes, int n_in,
                              void* d_out, int out_size) {
    (void)in_sizes; (void)n_in; (void)out_size;
    const float* x    = (const float*)d_in[0];
    const float* h    = (const float*)d_in[1];
    const float* Wih0 = (const float*)d_in[2];
    const float* Whh0 = (const float*)d_in[3];
    const float* bih0 = (const float*)d_in[4];
    const float* bhh0 = (const float*)d_in[5];
    const float* Wih1 = (const float*)d_in[6];
    const float* Whh1 = (const float*)d_in[7];
    const float* bih1 = (const float*)d_in[8];
    const float* bhh1 = (const float*)d_in[9];
    const float* Wout = (const float*)d_in[10];
    const float* bout = (const float*)d_in[11];

    // 148 blocks x 8 warps (4 pairs): 1024 active warps
    gru2_hmma_kernel<<<148, 256>>>(x, h, Wih0, Whh0, bih0, bhh0,
                                   Wih1, Whh1, bih1, bhh1, Wout, bout,
                                   (float*)d_out);
}